// round 16
// baseline (speedup 1.0000x reference)
#include <cuda_runtime.h>
#include <cuda_bf16.h>
#include <cuda_fp16.h>
#include <cstdint>

// GraphConvolution: out = relu(segment_sum((x @ W)[src] * ew, dst))
// R16 = R10 (114.5us best) verbatim EXCEPT:
//  - hist (GEMM tail) stores the atomicAdd-returned rank to g_rank[e]
//  - sort_scatter is atomic-free: pos = offs[dst] + rank[e]
//  - scan writes cursor[node] = start + degree (end offset) directly
// GEMM / scan structure / gather untouched.

#define N_NODES_MAX 100000
#define E_MAX       1600000
#define IN_F 256
#define OUT_F 64

#define SCAN_B 512
#define NBLK_MAX ((N_NODES_MAX + SCAN_B - 1) / SCAN_B)

__device__ __half             g_suph[N_NODES_MAX * OUT_F];
__device__ unsigned long long g_edges[E_MAX];
__device__ int                g_rank[E_MAX];
__device__ int                g_counts[N_NODES_MAX];
__device__ int                g_offs[N_NODES_MAX];
__device__ int                g_cursor[N_NODES_MAX];
__device__ unsigned long long g_tilest[NBLK_MAX];   // scan status: flag<<32 | value
__device__ unsigned int       g_ticket;

// ==================== helpers ====================
__device__ __forceinline__ uint32_t smem_u32(const void* p) {
    uint32_t a;
    asm("{ .reg .u64 t; cvta.to.shared.u64 t, %1; cvt.u32.u64 %0, t; }"
        : "=r"(a) : "l"(p));
    return a;
}

__device__ __forceinline__ void cp_async16(uint32_t dst, const void* src, int src_bytes) {
    asm volatile("cp.async.cg.shared.global [%0], [%1], 16, %2;"
                 :: "r"(dst), "l"(src), "r"(src_bytes));
}
#define CP_COMMIT() asm volatile("cp.async.commit_group;" ::: "memory")
#define CP_WAIT(n)  asm volatile("cp.async.wait_group %0;" :: "n"(n) : "memory")

__device__ __forceinline__ uint32_t bf2(float x, float y) {
    __nv_bfloat162 h = __floats2bfloat162_rn(x, y);
    return *reinterpret_cast<uint32_t*>(&h);
}
__device__ __forceinline__ float2 bf2f(uint32_t u) {
    __nv_bfloat162 h = *reinterpret_cast<__nv_bfloat162*>(&u);
    return __bfloat1622float2(h);
}

__device__ __forceinline__ void mma_bf16(float4& d,
    uint32_t a0, uint32_t a1, uint32_t a2, uint32_t a3,
    uint32_t b0, uint32_t b1)
{
    asm volatile(
        "mma.sync.aligned.m16n8k16.row.col.f32.bf16.bf16.f32 "
        "{%0,%1,%2,%3}, {%4,%5,%6,%7}, {%8,%9}, {%0,%1,%2,%3};"
        : "+f"(d.x), "+f"(d.y), "+f"(d.z), "+f"(d.w)
        : "r"(a0), "r"(a1), "r"(a2), "r"(a3), "r"(b0), "r"(b1));
}

// ==================== GEMM config (R10) ====================
#define KC_N   (IN_F / 16)       // 16
#define NT_N   (OUT_F / 8)       // 8
#define BTAB_ENTRIES (KC_N * NT_N * 32)
#define BTAB_BYTES   (BTAB_ENTRIES * 16)      // 65536

#define ROWS_CTA 256
#define KB       64
#define NKB      (IN_F / KB)     // 4
#define KC_PER_B (KB / 16)       // 4
#define ASTRIDE  68
#define ATILE_BYTES (ROWS_CTA * ASTRIDE * 4)  // 69632
#define SMEM_TOTAL (BTAB_BYTES + 2 * ATILE_BYTES) // 204800

#define HIST_BLOCKS 148

// ==================== GEMM (+ tail hist blocks) ====================
__global__ __launch_bounds__(512, 1) void gemm_hist_kernel(
    const float* __restrict__ x, const float* __restrict__ w,
    __half* __restrict__ suph, int N,
    const int* __restrict__ dst, int* __restrict__ counts,
    int* __restrict__ rank, int E,
    int gemm_blocks)
{
    const int tid  = threadIdx.x;

    // ---- hist role (tail-filler blocks); block 0 also resets scan state ----
    if ((int)blockIdx.x >= gemm_blocks) {
        int b = blockIdx.x - gemm_blocks;
        if (b == 0) {
            for (int i = tid; i < NBLK_MAX; i += 512) g_tilest[i] = 0ULL;
            if (tid == 0) g_ticket = 0u;
        }
        for (int e = b * 512 + tid; e < E; e += HIST_BLOCKS * 512) {
            int r = atomicAdd(&counts[dst[e]], 1);
            rank[e] = r;
        }
        return;
    }

    extern __shared__ char smem_raw[];
    float4* Bs = reinterpret_cast<float4*>(smem_raw);
    float*  As = reinterpret_cast<float*>(smem_raw + BTAB_BYTES);
    const uint32_t a_sbase = smem_u32(As);

    const int wid  = tid >> 5;
    const int lane = tid & 31;
    const int g    = lane >> 2;
    const int tig  = lane & 3;

    const int row0  = blockIdx.x * ROWS_CTA;
    const int rloc0 = wid * 16 + g;
    const int rloc1 = rloc0 + 8;
    const int r0 = row0 + rloc0;
    const int r1 = row0 + rloc1;

    auto stage = [&](int kb, int buf) {
        uint32_t abase = a_sbase + buf * ATILE_BYTES;
#pragma unroll
        for (int i = 0; i < 8; i++) {
            int idx = tid + i * 512;
            int r  = idx >> 4;
            int c4 = idx & 15;
            int grow = row0 + r;
            uint32_t d = abase + (uint32_t)(r * ASTRIDE + c4 * 4) * 4u;
            const float* srcp = &x[(size_t)(grow < N ? grow : 0) * IN_F + kb * KB + c4 * 4];
            cp_async16(d, srcp, grow < N ? 16 : 0);
        }
    };

    for (int idx = tid; idx < BTAB_ENTRIES; idx += 512) {
        int ln = idx & 31;
        int nt = (idx >> 5) & 7;
        int kc = idx >> 8;
        int gg  = ln >> 2;
        int tt  = ln & 3;
        int n  = nt * 8 + gg;
        int k0 = kc * 16 + 2 * tt;
        float w00 = w[(size_t)k0 * OUT_F + n];
        float w01 = w[(size_t)(k0 + 1) * OUT_F + n];
        float w10 = w[(size_t)(k0 + 8) * OUT_F + n];
        float w11 = w[(size_t)(k0 + 9) * OUT_F + n];
        uint32_t h0 = bf2(w00, w01);
        uint32_t h1 = bf2(w10, w11);
        float2 hf0 = bf2f(h0);
        float2 hf1 = bf2f(h1);
        uint32_t l0 = bf2(w00 - hf0.x, w01 - hf0.y);
        uint32_t l1 = bf2(w10 - hf1.x, w11 - hf1.y);
        Bs[idx] = make_float4(__uint_as_float(h0), __uint_as_float(h1),
                              __uint_as_float(l0), __uint_as_float(l1));
    }

    float4 acc[NT_N];
#pragma unroll
    for (int nt = 0; nt < NT_N; nt++) acc[nt] = make_float4(0.f, 0.f, 0.f, 0.f);

    stage(0, 0);
    CP_COMMIT();
    __syncthreads();

    for (int kb = 0; kb < NKB; kb++) {
        if (kb + 1 < NKB) {
            stage(kb + 1, (kb + 1) & 1);
            CP_COMMIT();
            CP_WAIT(1);
        } else {
            CP_WAIT(0);
        }
        __syncthreads();

        const float* Ab = As + (kb & 1) * (ROWS_CTA * ASTRIDE);

#pragma unroll
        for (int kcl = 0; kcl < KC_PER_B; kcl++) {
            const int kc = kb * KC_PER_B + kcl;
            const int c0 = kcl * 16 + 2 * tig;

            float2 a00 = *reinterpret_cast<const float2*>(&Ab[rloc0 * ASTRIDE + c0]);
            float2 a08 = *reinterpret_cast<const float2*>(&Ab[rloc0 * ASTRIDE + c0 + 8]);
            float2 a10 = *reinterpret_cast<const float2*>(&Ab[rloc1 * ASTRIDE + c0]);
            float2 a18 = *reinterpret_cast<const float2*>(&Ab[rloc1 * ASTRIDE + c0 + 8]);

            uint32_t ah0 = bf2(a00.x, a00.y);
            uint32_t ah1 = bf2(a10.x, a10.y);
            uint32_t ah2 = bf2(a08.x, a08.y);
            uint32_t ah3 = bf2(a18.x, a18.y);
            float2 f0 = bf2f(ah0), f1 = bf2f(ah1), f2 = bf2f(ah2), f3 = bf2f(ah3);
            uint32_t al0 = bf2(a00.x - f0.x, a00.y - f0.y);
            uint32_t al1 = bf2(a10.x - f1.x, a10.y - f1.y);
            uint32_t al2 = bf2(a08.x - f2.x, a08.y - f2.y);
            uint32_t al3 = bf2(a18.x - f3.x, a18.y - f3.y);

            const float4* brow = &Bs[(kc * NT_N) * 32 + lane];
#pragma unroll
            for (int nt = 0; nt < NT_N; nt++) {
                float4 b = brow[nt * 32];
                uint32_t bh0 = __float_as_uint(b.x);
                uint32_t bh1 = __float_as_uint(b.y);
                uint32_t bl0 = __float_as_uint(b.z);
                uint32_t bl1 = __float_as_uint(b.w);
                mma_bf16(acc[nt], ah0, ah1, ah2, ah3, bh0, bh1);
                mma_bf16(acc[nt], ah0, ah1, ah2, ah3, bl0, bl1);
                mma_bf16(acc[nt], al0, al1, al2, al3, bh0, bh1);
            }
        }
        __syncthreads();
    }

    // ---- epilogue: store fp16 support ----
#pragma unroll
    for (int nt = 0; nt < NT_N; nt++) {
        int col = nt * 8 + tig * 2;
        if (r0 < N) {
            __half2 h = __floats2half2_rn(acc[nt].x, acc[nt].y);
            *reinterpret_cast<__half2*>(&suph[(size_t)r0 * OUT_F + col]) = h;
        }
        if (r1 < N) {
            __half2 h = __floats2half2_rn(acc[nt].z, acc[nt].w);
            *reinterpret_cast<__half2*>(&suph[(size_t)r1 * OUT_F + col]) = h;
        }
    }
}

// ==================== fused scan (decoupled lookback) ====================
__global__ __launch_bounds__(SCAN_B) void scan_fused_kernel(
    int* __restrict__ counts, int* __restrict__ offs,
    int* __restrict__ cursor, int N)
{
    __shared__ int sbid;
    __shared__ int wsum[16];
    __shared__ int sprefix;

    const int tid  = threadIdx.x;
    const int lane = tid & 31;
    const int wid  = tid >> 5;

    if (tid == 0) sbid = (int)atomicAdd(&g_ticket, 1u);
    __syncthreads();
    const int bid = sbid;
    const int gid = bid * SCAN_B + tid;

    int v = (gid < N) ? counts[gid] : 0;
    int inc = v;
#pragma unroll
    for (int d = 1; d < 32; d <<= 1) {
        int t = __shfl_up_sync(0xFFFFFFFF, inc, d);
        if (lane >= d) inc += t;
    }
    if (lane == 31) wsum[wid] = inc;
    __syncthreads();
    if (wid == 0) {
        int s = (lane < 16) ? wsum[lane] : 0;
#pragma unroll
        for (int d = 1; d < 16; d <<= 1) {
            int t = __shfl_up_sync(0xFFFFFFFF, s, d);
            if (lane >= d) s += t;
        }
        if (lane < 16) wsum[lane] = s;
    }
    __syncthreads();
    const int block_total = wsum[15];

    if (tid == 0) {
        if (bid == 0) {
            atomicExch(&g_tilest[0], (2ULL << 32) | (unsigned)block_total);
            sprefix = 0;
        } else {
            atomicExch(&g_tilest[bid], (1ULL << 32) | (unsigned)block_total);
            int prefix = 0;
            int p = bid - 1;
            while (true) {
                unsigned long long s = atomicAdd(&g_tilest[p], 0ULL);
                unsigned flag = (unsigned)(s >> 32);
                if (flag == 2u) { prefix += (int)(unsigned)s; break; }
                if (flag == 1u) { prefix += (int)(unsigned)s; p--; }
            }
            atomicExch(&g_tilest[bid],
                       (2ULL << 32) | (unsigned)(prefix + block_total));
            sprefix = prefix;
        }
    }
    __syncthreads();

    const int base = sprefix + ((wid > 0) ? wsum[wid - 1] : 0);
    if (gid < N) {
        int o = base + inc - v;
        offs[gid]   = o;
        cursor[gid] = o + v;   // END offset (start + degree) for the gather
        counts[gid] = 0;       // restore for next launch
    }
}

// ============== sort scatter: atomic-free via precomputed ranks ==============
__global__ void sort_scatter_kernel(
    const int* __restrict__ src, const int* __restrict__ dst,
    const float* __restrict__ ew, const int* __restrict__ offs,
    const int* __restrict__ rank,
    unsigned long long* __restrict__ es, int E)
{
    int i = blockIdx.x * blockDim.x + threadIdx.x;
    int e0 = i * 2;
    int e1 = e0 + 1;
    if (e1 < E) {
        int d0 = __ldg(&dst[e0]);
        int d1 = __ldg(&dst[e1]);
        int p0 = __ldg(&offs[d0]) + __ldg(&rank[e0]);
        int p1 = __ldg(&offs[d1]) + __ldg(&rank[e1]);
        unsigned long long v0 = (unsigned int)__ldg(&src[e0])
            | ((unsigned long long)__float_as_uint(__ldg(&ew[e0])) << 32);
        unsigned long long v1 = (unsigned int)__ldg(&src[e1])
            | ((unsigned long long)__float_as_uint(__ldg(&ew[e1])) << 32);
        es[p0] = v0;
        es[p1] = v1;
    } else if (e0 < E) {
        int d0 = __ldg(&dst[e0]);
        int p0 = __ldg(&offs[d0]) + __ldg(&rank[e0]);
        unsigned long long v0 = (unsigned int)__ldg(&src[e0])
            | ((unsigned long long)__float_as_uint(__ldg(&ew[e0])) << 32);
        es[p0] = v0;
    }
}

// ==================== gather + relu (verbatim R10) ====================
__global__ __launch_bounds__(256) void gather_kernel(
    const __half* __restrict__ suph,
    const unsigned long long* __restrict__ es,
    const int* __restrict__ offs, const int* __restrict__ cursor,
    float* __restrict__ out, int N)
{
    int group = threadIdx.x >> 3;          // 32 nodes per block
    int lane  = threadIdx.x & 7;           // 8 halves each
    int node = blockIdx.x * 32 + group;
    if (node >= N) return;

    int start = offs[node];
    int end   = cursor[node];              // end offset (start + degree)

    float acc[8];
#pragma unroll
    for (int i = 0; i < 8; i++) acc[i] = 0.f;

    auto fma_edge = [&](unsigned long long p) {
        int   s = (int)(unsigned int)p;
        float wgt = __uint_as_float((unsigned int)(p >> 32));
        uint4 v = *reinterpret_cast<const uint4*>(&suph[(size_t)s * OUT_F + lane * 8]);
        float2 f0 = __half22float2(*reinterpret_cast<__half2*>(&v.x));
        float2 f1 = __half22float2(*reinterpret_cast<__half2*>(&v.y));
        float2 f2 = __half22float2(*reinterpret_cast<__half2*>(&v.z));
        float2 f3 = __half22float2(*reinterpret_cast<__half2*>(&v.w));
        acc[0] = fmaf(f0.x, wgt, acc[0]); acc[1] = fmaf(f0.y, wgt, acc[1]);
        acc[2] = fmaf(f1.x, wgt, acc[2]); acc[3] = fmaf(f1.y, wgt, acc[3]);
        acc[4] = fmaf(f2.x, wgt, acc[4]); acc[5] = fmaf(f2.y, wgt, acc[5]);
        acc[6] = fmaf(f3.x, wgt, acc[6]); acc[7] = fmaf(f3.y, wgt, acc[7]);
    };

    int e = start;
    for (; e + 4 <= end; e += 4) {
        unsigned long long p0 = __ldg(&es[e]);
        unsigned long long p1 = __ldg(&es[e + 1]);
        unsigned long long p2 = __ldg(&es[e + 2]);
        unsigned long long p3 = __ldg(&es[e + 3]);
        fma_edge(p0); fma_edge(p1); fma_edge(p2); fma_edge(p3);
    }
    for (; e < end; e++) fma_edge(__ldg(&es[e]));

    float4 o0 = make_float4(fmaxf(acc[0], 0.f), fmaxf(acc[1], 0.f),
                            fmaxf(acc[2], 0.f), fmaxf(acc[3], 0.f));
    float4 o1 = make_float4(fmaxf(acc[4], 0.f), fmaxf(acc[5], 0.f),
                            fmaxf(acc[6], 0.f), fmaxf(acc[7], 0.f));
    float* op = &out[(size_t)node * OUT_F + lane * 8];
    *reinterpret_cast<float4*>(op)     = o0;
    *reinterpret_cast<float4*>(op + 4) = o1;
}

extern "C" void kernel_launch(void* const* d_in, const int* in_sizes, int n_in,
                              void* d_out, int out_size)
{
    const float* x    = (const float*)d_in[0];
    const float* w    = (const float*)d_in[1];
    const int*   src  = (const int*)d_in[2];
    const int*   dst  = (const int*)d_in[3];
    const float* ew   = (const float*)d_in[4];
    float* out = (float*)d_out;

    const int N = in_sizes[0] / IN_F;
    const int E = in_sizes[2];

    __half* suph;              cudaGetSymbolAddress((void**)&suph, g_suph);
    unsigned long long* es;    cudaGetSymbolAddress((void**)&es, g_edges);
    int* rank;                 cudaGetSymbolAddress((void**)&rank, g_rank);
    int* counts;               cudaGetSymbolAddress((void**)&counts, g_counts);
    int* offs;                 cudaGetSymbolAddress((void**)&offs, g_offs);
    int* cursor;               cudaGetSymbolAddress((void**)&cursor, g_cursor);

    const int nb = (N + SCAN_B - 1) / SCAN_B;
    const int gemm_blocks = (N + ROWS_CTA - 1) / ROWS_CTA;

    // 1) GEMM + hist-with-ranks (+ scan-state reset in hist block 0)
    cudaFuncSetAttribute(gemm_hist_kernel,
                         cudaFuncAttributeMaxDynamicSharedMemorySize, SMEM_TOTAL);
    gemm_hist_kernel<<<gemm_blocks + HIST_BLOCKS, 512, SMEM_TOTAL>>>(
        x, w, suph, N, dst, counts, rank, E, gemm_blocks);

    // 2) scan + atomic-free sort
    scan_fused_kernel<<<nb, SCAN_B>>>(counts, offs, cursor, N);
    sort_scatter_kernel<<<(E / 2 + 256) / 256, 256>>>(src, dst, ew, offs, rank, es, E);

    // 3) gather + relu (R10 layout)
    gather_kernel<<<(N + 31) / 32, 256>>>(suph, es, offs, cursor, out, N);
}

// round 17
// speedup vs baseline: 1.1034x; 1.1034x over previous
#include <cuda_runtime.h>
#include <cuda_bf16.h>
#include <cuda_fp16.h>
#include <cstdint>

// GraphConvolution: out = relu(segment_sum((x @ W)[src] * ew, dst))
// R17 = R10 (114.5us best) byte-for-byte EXCEPT sort_scatter processes
// 2 edges/thread (doubles atomic/store MLP; measured ~+1.7us in R11/R13
// decompositions). No other change.

#define N_NODES_MAX 100000
#define E_MAX       1600000
#define IN_F 256
#define OUT_F 64

#define SCAN_B 512
#define NBLK_MAX ((N_NODES_MAX + SCAN_B - 1) / SCAN_B)

__device__ __half             g_suph[N_NODES_MAX * OUT_F];
__device__ unsigned long long g_edges[E_MAX];
__device__ int                g_counts[N_NODES_MAX];
__device__ int                g_offs[N_NODES_MAX];
__device__ int                g_cursor[N_NODES_MAX];
__device__ unsigned long long g_tilest[NBLK_MAX];   // scan status: flag<<32 | value
__device__ unsigned int       g_ticket;

// ==================== helpers ====================
__device__ __forceinline__ uint32_t smem_u32(const void* p) {
    uint32_t a;
    asm("{ .reg .u64 t; cvta.to.shared.u64 t, %1; cvt.u32.u64 %0, t; }"
        : "=r"(a) : "l"(p));
    return a;
}

__device__ __forceinline__ void cp_async16(uint32_t dst, const void* src, int src_bytes) {
    asm volatile("cp.async.cg.shared.global [%0], [%1], 16, %2;"
                 :: "r"(dst), "l"(src), "r"(src_bytes));
}
#define CP_COMMIT() asm volatile("cp.async.commit_group;" ::: "memory")
#define CP_WAIT(n)  asm volatile("cp.async.wait_group %0;" :: "n"(n) : "memory")

__device__ __forceinline__ uint32_t bf2(float x, float y) {
    __nv_bfloat162 h = __floats2bfloat162_rn(x, y);
    return *reinterpret_cast<uint32_t*>(&h);
}
__device__ __forceinline__ float2 bf2f(uint32_t u) {
    __nv_bfloat162 h = *reinterpret_cast<__nv_bfloat162*>(&u);
    return __bfloat1622float2(h);
}

__device__ __forceinline__ void mma_bf16(float4& d,
    uint32_t a0, uint32_t a1, uint32_t a2, uint32_t a3,
    uint32_t b0, uint32_t b1)
{
    asm volatile(
        "mma.sync.aligned.m16n8k16.row.col.f32.bf16.bf16.f32 "
        "{%0,%1,%2,%3}, {%4,%5,%6,%7}, {%8,%9}, {%0,%1,%2,%3};"
        : "+f"(d.x), "+f"(d.y), "+f"(d.z), "+f"(d.w)
        : "r"(a0), "r"(a1), "r"(a2), "r"(a3), "r"(b0), "r"(b1));
}

// ==================== GEMM config ====================
#define KC_N   (IN_F / 16)       // 16
#define NT_N   (OUT_F / 8)       // 8
#define BTAB_ENTRIES (KC_N * NT_N * 32)
#define BTAB_BYTES   (BTAB_ENTRIES * 16)      // 65536

#define ROWS_CTA 256
#define KB       64
#define NKB      (IN_F / KB)     // 4
#define KC_PER_B (KB / 16)       // 4
#define ASTRIDE  68
#define ATILE_BYTES (ROWS_CTA * ASTRIDE * 4)  // 69632
#define SMEM_TOTAL (BTAB_BYTES + 2 * ATILE_BYTES) // 204800

#define HIST_BLOCKS 148

// ==================== GEMM (+ tail hist blocks) ====================
__global__ __launch_bounds__(512, 1) void gemm_hist_kernel(
    const float* __restrict__ x, const float* __restrict__ w,
    __half* __restrict__ suph, int N,
    const int* __restrict__ dst, int* __restrict__ counts, int E,
    int gemm_blocks)
{
    const int tid  = threadIdx.x;

    // ---- hist role (tail-filler blocks); block 0 also resets scan state ----
    if ((int)blockIdx.x >= gemm_blocks) {
        int b = blockIdx.x - gemm_blocks;
        if (b == 0) {
            for (int i = tid; i < NBLK_MAX; i += 512) g_tilest[i] = 0ULL;
            if (tid == 0) g_ticket = 0u;
        }
        for (int e = b * 512 + tid; e < E; e += HIST_BLOCKS * 512)
            atomicAdd(&counts[dst[e]], 1);
        return;
    }

    extern __shared__ char smem_raw[];
    float4* Bs = reinterpret_cast<float4*>(smem_raw);
    float*  As = reinterpret_cast<float*>(smem_raw + BTAB_BYTES);
    const uint32_t a_sbase = smem_u32(As);

    const int wid  = tid >> 5;
    const int lane = tid & 31;
    const int g    = lane >> 2;
    const int tig  = lane & 3;

    const int row0  = blockIdx.x * ROWS_CTA;
    const int rloc0 = wid * 16 + g;
    const int rloc1 = rloc0 + 8;
    const int r0 = row0 + rloc0;
    const int r1 = row0 + rloc1;

    auto stage = [&](int kb, int buf) {
        uint32_t abase = a_sbase + buf * ATILE_BYTES;
#pragma unroll
        for (int i = 0; i < 8; i++) {
            int idx = tid + i * 512;
            int r  = idx >> 4;
            int c4 = idx & 15;
            int grow = row0 + r;
            uint32_t d = abase + (uint32_t)(r * ASTRIDE + c4 * 4) * 4u;
            const float* srcp = &x[(size_t)(grow < N ? grow : 0) * IN_F + kb * KB + c4 * 4];
            cp_async16(d, srcp, grow < N ? 16 : 0);
        }
    };

    for (int idx = tid; idx < BTAB_ENTRIES; idx += 512) {
        int ln = idx & 31;
        int nt = (idx >> 5) & 7;
        int kc = idx >> 8;
        int gg  = ln >> 2;
        int tt  = ln & 3;
        int n  = nt * 8 + gg;
        int k0 = kc * 16 + 2 * tt;
        float w00 = w[(size_t)k0 * OUT_F + n];
        float w01 = w[(size_t)(k0 + 1) * OUT_F + n];
        float w10 = w[(size_t)(k0 + 8) * OUT_F + n];
        float w11 = w[(size_t)(k0 + 9) * OUT_F + n];
        uint32_t h0 = bf2(w00, w01);
        uint32_t h1 = bf2(w10, w11);
        float2 hf0 = bf2f(h0);
        float2 hf1 = bf2f(h1);
        uint32_t l0 = bf2(w00 - hf0.x, w01 - hf0.y);
        uint32_t l1 = bf2(w10 - hf1.x, w11 - hf1.y);
        Bs[idx] = make_float4(__uint_as_float(h0), __uint_as_float(h1),
                              __uint_as_float(l0), __uint_as_float(l1));
    }

    float4 acc[NT_N];
#pragma unroll
    for (int nt = 0; nt < NT_N; nt++) acc[nt] = make_float4(0.f, 0.f, 0.f, 0.f);

    stage(0, 0);
    CP_COMMIT();
    __syncthreads();

    for (int kb = 0; kb < NKB; kb++) {
        if (kb + 1 < NKB) {
            stage(kb + 1, (kb + 1) & 1);
            CP_COMMIT();
            CP_WAIT(1);
        } else {
            CP_WAIT(0);
        }
        __syncthreads();

        const float* Ab = As + (kb & 1) * (ROWS_CTA * ASTRIDE);

#pragma unroll
        for (int kcl = 0; kcl < KC_PER_B; kcl++) {
            const int kc = kb * KC_PER_B + kcl;
            const int c0 = kcl * 16 + 2 * tig;

            float2 a00 = *reinterpret_cast<const float2*>(&Ab[rloc0 * ASTRIDE + c0]);
            float2 a08 = *reinterpret_cast<const float2*>(&Ab[rloc0 * ASTRIDE + c0 + 8]);
            float2 a10 = *reinterpret_cast<const float2*>(&Ab[rloc1 * ASTRIDE + c0]);
            float2 a18 = *reinterpret_cast<const float2*>(&Ab[rloc1 * ASTRIDE + c0 + 8]);

            uint32_t ah0 = bf2(a00.x, a00.y);
            uint32_t ah1 = bf2(a10.x, a10.y);
            uint32_t ah2 = bf2(a08.x, a08.y);
            uint32_t ah3 = bf2(a18.x, a18.y);
            float2 f0 = bf2f(ah0), f1 = bf2f(ah1), f2 = bf2f(ah2), f3 = bf2f(ah3);
            uint32_t al0 = bf2(a00.x - f0.x, a00.y - f0.y);
            uint32_t al1 = bf2(a10.x - f1.x, a10.y - f1.y);
            uint32_t al2 = bf2(a08.x - f2.x, a08.y - f2.y);
            uint32_t al3 = bf2(a18.x - f3.x, a18.y - f3.y);

            const float4* brow = &Bs[(kc * NT_N) * 32 + lane];
#pragma unroll
            for (int nt = 0; nt < NT_N; nt++) {
                float4 b = brow[nt * 32];
                uint32_t bh0 = __float_as_uint(b.x);
                uint32_t bh1 = __float_as_uint(b.y);
                uint32_t bl0 = __float_as_uint(b.z);
                uint32_t bl1 = __float_as_uint(b.w);
                mma_bf16(acc[nt], ah0, ah1, ah2, ah3, bh0, bh1);
                mma_bf16(acc[nt], ah0, ah1, ah2, ah3, bl0, bl1);
                mma_bf16(acc[nt], al0, al1, al2, al3, bh0, bh1);
            }
        }
        __syncthreads();
    }

    // ---- epilogue: store fp16 support ----
#pragma unroll
    for (int nt = 0; nt < NT_N; nt++) {
        int col = nt * 8 + tig * 2;
        if (r0 < N) {
            __half2 h = __floats2half2_rn(acc[nt].x, acc[nt].y);
            *reinterpret_cast<__half2*>(&suph[(size_t)r0 * OUT_F + col]) = h;
        }
        if (r1 < N) {
            __half2 h = __floats2half2_rn(acc[nt].z, acc[nt].w);
            *reinterpret_cast<__half2*>(&suph[(size_t)r1 * OUT_F + col]) = h;
        }
    }
}

// ==================== fused scan (decoupled lookback) ====================
__global__ __launch_bounds__(SCAN_B) void scan_fused_kernel(
    int* __restrict__ counts, int* __restrict__ offs,
    int* __restrict__ cursor, int N)
{
    __shared__ int sbid;
    __shared__ int wsum[16];
    __shared__ int sprefix;

    const int tid  = threadIdx.x;
    const int lane = tid & 31;
    const int wid  = tid >> 5;

    if (tid == 0) sbid = (int)atomicAdd(&g_ticket, 1u);
    __syncthreads();
    const int bid = sbid;
    const int gid = bid * SCAN_B + tid;

    int v = (gid < N) ? counts[gid] : 0;
    int inc = v;
#pragma unroll
    for (int d = 1; d < 32; d <<= 1) {
        int t = __shfl_up_sync(0xFFFFFFFF, inc, d);
        if (lane >= d) inc += t;
    }
    if (lane == 31) wsum[wid] = inc;
    __syncthreads();
    if (wid == 0) {
        int s = (lane < 16) ? wsum[lane] : 0;
#pragma unroll
        for (int d = 1; d < 16; d <<= 1) {
            int t = __shfl_up_sync(0xFFFFFFFF, s, d);
            if (lane >= d) s += t;
        }
        if (lane < 16) wsum[lane] = s;
    }
    __syncthreads();
    const int block_total = wsum[15];

    if (tid == 0) {
        if (bid == 0) {
            atomicExch(&g_tilest[0], (2ULL << 32) | (unsigned)block_total);
            sprefix = 0;
        } else {
            atomicExch(&g_tilest[bid], (1ULL << 32) | (unsigned)block_total);
            int prefix = 0;
            int p = bid - 1;
            while (true) {
                unsigned long long s = atomicAdd(&g_tilest[p], 0ULL);
                unsigned flag = (unsigned)(s >> 32);
                if (flag == 2u) { prefix += (int)(unsigned)s; break; }
                if (flag == 1u) { prefix += (int)(unsigned)s; p--; }
            }
            atomicExch(&g_tilest[bid],
                       (2ULL << 32) | (unsigned)(prefix + block_total));
            sprefix = prefix;
        }
    }
    __syncthreads();

    const int base = sprefix + ((wid > 0) ? wsum[wid - 1] : 0);
    if (gid < N) {
        int o = base + inc - v;
        offs[gid]   = o;
        cursor[gid] = o;
        counts[gid] = 0;   // restore for next launch
    }
}

// ==================== sort scatter: 2 edges/thread ====================
__global__ void sort_scatter_kernel(
    const int* __restrict__ src, const int* __restrict__ dst,
    const float* __restrict__ ew, int* __restrict__ cursor,
    unsigned long long* __restrict__ es, int E)
{
    int i = blockIdx.x * blockDim.x + threadIdx.x;
    int e0 = i * 2;
    int e1 = e0 + 1;
    if (e1 < E) {
        int d0 = dst[e0];
        int d1 = dst[e1];
        unsigned long long p0 = (unsigned int)src[e0]
            | ((unsigned long long)__float_as_uint(ew[e0]) << 32);
        unsigned long long p1 = (unsigned int)src[e1]
            | ((unsigned long long)__float_as_uint(ew[e1]) << 32);
        int pos0 = atomicAdd(&cursor[d0], 1);
        int pos1 = atomicAdd(&cursor[d1], 1);
        es[pos0] = p0;
        es[pos1] = p1;
    } else if (e0 < E) {
        int d0 = dst[e0];
        unsigned long long p0 = (unsigned int)src[e0]
            | ((unsigned long long)__float_as_uint(ew[e0]) << 32);
        int pos0 = atomicAdd(&cursor[d0], 1);
        es[pos0] = p0;
    }
}

// ==================== gather + relu (verbatim R10) ====================
__global__ __launch_bounds__(256) void gather_kernel(
    const __half* __restrict__ suph,
    const unsigned long long* __restrict__ es,
    const int* __restrict__ offs, const int* __restrict__ cursor,
    float* __restrict__ out, int N)
{
    int group = threadIdx.x >> 3;          // 32 nodes per block
    int lane  = threadIdx.x & 7;           // 8 halves each
    int node = blockIdx.x * 32 + group;
    if (node >= N) return;

    int start = offs[node];
    int end   = cursor[node];              // post-sort cursor == end offset

    float acc[8];
#pragma unroll
    for (int i = 0; i < 8; i++) acc[i] = 0.f;

    auto fma_edge = [&](unsigned long long p) {
        int   s = (int)(unsigned int)p;
        float wgt = __uint_as_float((unsigned int)(p >> 32));
        uint4 v = *reinterpret_cast<const uint4*>(&suph[(size_t)s * OUT_F + lane * 8]);
        float2 f0 = __half22float2(*reinterpret_cast<__half2*>(&v.x));
        float2 f1 = __half22float2(*reinterpret_cast<__half2*>(&v.y));
        float2 f2 = __half22float2(*reinterpret_cast<__half2*>(&v.z));
        float2 f3 = __half22float2(*reinterpret_cast<__half2*>(&v.w));
        acc[0] = fmaf(f0.x, wgt, acc[0]); acc[1] = fmaf(f0.y, wgt, acc[1]);
        acc[2] = fmaf(f1.x, wgt, acc[2]); acc[3] = fmaf(f1.y, wgt, acc[3]);
        acc[4] = fmaf(f2.x, wgt, acc[4]); acc[5] = fmaf(f2.y, wgt, acc[5]);
        acc[6] = fmaf(f3.x, wgt, acc[6]); acc[7] = fmaf(f3.y, wgt, acc[7]);
    };

    int e = start;
    for (; e + 4 <= end; e += 4) {
        unsigned long long p0 = __ldg(&es[e]);
        unsigned long long p1 = __ldg(&es[e + 1]);
        unsigned long long p2 = __ldg(&es[e + 2]);
        unsigned long long p3 = __ldg(&es[e + 3]);
        fma_edge(p0); fma_edge(p1); fma_edge(p2); fma_edge(p3);
    }
    for (; e < end; e++) fma_edge(__ldg(&es[e]));

    float4 o0 = make_float4(fmaxf(acc[0], 0.f), fmaxf(acc[1], 0.f),
                            fmaxf(acc[2], 0.f), fmaxf(acc[3], 0.f));
    float4 o1 = make_float4(fmaxf(acc[4], 0.f), fmaxf(acc[5], 0.f),
                            fmaxf(acc[6], 0.f), fmaxf(acc[7], 0.f));
    float* op = &out[(size_t)node * OUT_F + lane * 8];
    *reinterpret_cast<float4*>(op)     = o0;
    *reinterpret_cast<float4*>(op + 4) = o1;
}

extern "C" void kernel_launch(void* const* d_in, const int* in_sizes, int n_in,
                              void* d_out, int out_size)
{
    const float* x    = (const float*)d_in[0];
    const float* w    = (const float*)d_in[1];
    const int*   src  = (const int*)d_in[2];
    const int*   dst  = (const int*)d_in[3];
    const float* ew   = (const float*)d_in[4];
    float* out = (float*)d_out;

    const int N = in_sizes[0] / IN_F;
    const int E = in_sizes[2];

    __half* suph;              cudaGetSymbolAddress((void**)&suph, g_suph);
    unsigned long long* es;    cudaGetSymbolAddress((void**)&es, g_edges);
    int* counts;               cudaGetSymbolAddress((void**)&counts, g_counts);
    int* offs;                 cudaGetSymbolAddress((void**)&offs, g_offs);
    int* cursor;               cudaGetSymbolAddress((void**)&cursor, g_cursor);

    const int nb = (N + SCAN_B - 1) / SCAN_B;
    const int gemm_blocks = (N + ROWS_CTA - 1) / ROWS_CTA;

    // 1) GEMM + hist (+ scan-state reset in hist block 0)
    cudaFuncSetAttribute(gemm_hist_kernel,
                         cudaFuncAttributeMaxDynamicSharedMemorySize, SMEM_TOTAL);
    gemm_hist_kernel<<<gemm_blocks + HIST_BLOCKS, 512, SMEM_TOTAL>>>(
        x, w, suph, N, dst, counts, E, gemm_blocks);

    // 2) scan + sort (2 edges/thread)
    scan_fused_kernel<<<nb, SCAN_B>>>(counts, offs, cursor, N);
    sort_scatter_kernel<<<(E / 2 + 256) / 256, 256>>>(src, dst, ew, cursor, es, E);

    // 3) gather + relu (R10 layout)
    gather_kernel<<<(N + 31) / 32, 256>>>(suph, es, offs, cursor, out, N);
}